// round 3
// baseline (speedup 1.0000x reference)
#include <cuda_runtime.h>
#include <cuda_fp16.h>
#include <cstdint>

// ---------------------------------------------------------------------------
// Problem constants
// ---------------------------------------------------------------------------
#define B_   32
#define LQ_  300
#define D_   256
#define H_   8
#define L_   3
#define P_   4
#define HD_  32
#define LV_  8400   // 80*80 + 40*40 + 20*20

// ---------------------------------------------------------------------------
// Scratch (device globals)
// ---------------------------------------------------------------------------
__device__ __half g_vhalf[(size_t)B_ * LV_ * D_];                // 137.6 MB
__device__ float  g_qf  [(size_t)B_ * LQ_ * 288];                // fused off|attn
__device__ float  g_samp[(size_t)B_ * LQ_ * D_];                 // [9600,256]
__device__ float  g_Wqf [256 * 288];                             // fused weights
__device__ float  g_bqf [288];                                   // fused bias

// ---------------------------------------------------------------------------
// fp32 -> fp16 value conversion (8 floats / thread)
// ---------------------------------------------------------------------------
__global__ __launch_bounds__(256)
void f2h_kernel(const float* __restrict__ in, __half* __restrict__ out, int n8)
{
    int i = blockIdx.x * blockDim.x + threadIdx.x;
    if (i >= n8) return;
    float4 a = ((const float4*)in)[2 * i];
    float4 b = ((const float4*)in)[2 * i + 1];
    uint4 o;
    half2 p;
    p = __floats2half2_rn(a.x, a.y); o.x = *(unsigned*)&p;
    p = __floats2half2_rn(a.z, a.w); o.y = *(unsigned*)&p;
    p = __floats2half2_rn(b.x, b.y); o.z = *(unsigned*)&p;
    p = __floats2half2_rn(b.z, b.w); o.w = *(unsigned*)&p;
    ((uint4*)out)[i] = o;
}

// ---------------------------------------------------------------------------
// Build fused query-side weights: Wqf[256,288] = [Woff | Wattn], bqf = [boff|battn]
// ---------------------------------------------------------------------------
__global__ __launch_bounds__(256)
void prep_weights_kernel(const float* __restrict__ Woff, const float* __restrict__ boff,
                         const float* __restrict__ Wattn, const float* __restrict__ battn,
                         float* __restrict__ Wqf, float* __restrict__ bqf)
{
    int i = blockIdx.x * blockDim.x + threadIdx.x;   // [0, 256*288)
    if (i < 256 * 288) {
        int k = i / 288, j = i % 288;
        Wqf[i] = (j < 192) ? Woff[k * 192 + j] : Wattn[k * 96 + (j - 192)];
    }
    if (i < 288)
        bqf[i] = (i < 192) ? boff[i] : battn[i - 192];
}

// ---------------------------------------------------------------------------
// Tiled GEMM:  C[M,N] = A[M,K] @ W[K,N] + bias[N]
// ---------------------------------------------------------------------------
#define BM 64
#define BN 64
#define BK 16

__global__ __launch_bounds__(256)
void gemm_bias_kernel(const float* __restrict__ A, const float* __restrict__ W,
                      const float* __restrict__ bias, float* __restrict__ C,
                      int M, int N, int K)
{
    __shared__ float As[BK][BM + 1];
    __shared__ float Bs[BK][BN];

    const int tid = threadIdx.x;
    const int m0  = blockIdx.y * BM;
    const int n0  = blockIdx.x * BN;
    const int ty  = tid >> 4;
    const int tx  = tid & 15;

    float acc[4][4];
#pragma unroll
    for (int i = 0; i < 4; i++)
#pragma unroll
        for (int j = 0; j < 4; j++) acc[i][j] = 0.f;

    for (int k0 = 0; k0 < K; k0 += BK) {
#pragma unroll
        for (int t = 0; t < 4; t++) {
            int idx = tid + t * 256;
            int m = idx >> 4;
            int k = idx & 15;
            int gm = m0 + m;
            As[k][m] = (gm < M) ? A[(size_t)gm * K + (k0 + k)] : 0.f;
        }
#pragma unroll
        for (int t = 0; t < 4; t++) {
            int idx = tid + t * 256;
            int k = idx >> 6;
            int n = idx & 63;
            int gn = n0 + n;
            Bs[k][n] = (gn < N) ? W[(size_t)(k0 + k) * N + gn] : 0.f;
        }
        __syncthreads();

#pragma unroll
        for (int k = 0; k < BK; k++) {
            float a[4], b[4];
#pragma unroll
            for (int i = 0; i < 4; i++) a[i] = As[k][ty + i * 16];
#pragma unroll
            for (int j = 0; j < 4; j++) b[j] = Bs[k][tx + j * 16];
#pragma unroll
            for (int i = 0; i < 4; i++)
#pragma unroll
                for (int j = 0; j < 4; j++)
                    acc[i][j] += a[i] * b[j];
        }
        __syncthreads();
    }

#pragma unroll
    for (int i = 0; i < 4; i++) {
        int gm = m0 + ty + i * 16;
        if (gm >= M) continue;
#pragma unroll
        for (int j = 0; j < 4; j++) {
            int gn = n0 + tx + j * 16;
            if (gn < N)
                C[(size_t)gm * N + gn] = acc[i][j] + bias[gn];
        }
    }
}

// ---------------------------------------------------------------------------
// Fused sampling (fp16 value) + per-head Wv projection.
// Linearity: sampled_h = (sum cw * value[idx]) @ Wv_h + wsum * bv_h
// Warp <-> (b,q); blockIdx.x = head. Lane owns 8 channels (one uint4 = 8 halves).
// ---------------------------------------------------------------------------
#define QW 8   // queries (warps) per block

__global__ __launch_bounds__(256)
void sample_fused_kernel(const float* __restrict__ rp,
                         const float* __restrict__ qf,      // [9600, 288] off|attn
                         const __half* __restrict__ vhalf,  // [B, LV, 256] fp16
                         const float* __restrict__ Wv,      // [256, 256]
                         const float* __restrict__ bv,      // [256]
                         float* __restrict__ samp)          // [9600, 256]
{
    __shared__ float sWv[256][32];   // 32 KB
    __shared__ float sraw[QW][256];  // 8 KB

    const int h    = blockIdx.x;
    const int tid  = threadIdx.x;
    const int warp = tid >> 5;
    const int lane = tid & 31;

    {
        const float* wvh = Wv + h * HD_;
#pragma unroll
        for (int t = 0; t < 32; t++) {
            int i = tid + t * 256;
            int c = i >> 5, j = i & 31;
            sWv[c][j] = wvh[(size_t)c * D_ + j];
        }
    }

    const int bq = blockIdx.y * QW + warp;
    const int b  = bq / LQ_;

    // softmax over 12 logits (lane-redundant)
    const float* al = qf + (size_t)bq * 288 + 192 + h * (L_ * P_);
    float w[L_ * P_];
    float mx = -1e30f;
#pragma unroll
    for (int i = 0; i < L_ * P_; i++) { w[i] = al[i]; mx = fmaxf(mx, w[i]); }
    float ssum = 0.f;
#pragma unroll
    for (int i = 0; i < L_ * P_; i++) { w[i] = __expf(w[i] - mx); ssum += w[i]; }
    const float inv = 1.f / ssum;

    const float* offp = qf + (size_t)bq * 288 + h * (L_ * P_ * 2);
    const float* rpp  = rp + (size_t)bq * (L_ * 4);
    const uint4* vb   = (const uint4*)(vhalf + (size_t)b * LV_ * D_);  // row = 32 uint4

    float acc[8];
#pragma unroll
    for (int i = 0; i < 8; i++) acc[i] = 0.f;
    float wsum = 0.f;

    const int HsA[3] = {80, 40, 20};
    const int stA[3] = {0, 6400, 8000};

#pragma unroll
    for (int l = 0; l < L_; l++) {
        const float cx = rpp[l * 4 + 0];
        const float cy = rpp[l * 4 + 1];
        const float hw = rpp[l * 4 + 2] * 0.5f;
        const float hh = rpp[l * 4 + 3] * 0.5f;
        const int Wl = HsA[l], Hl = HsA[l], s0 = stA[l];

#pragma unroll
        for (int p = 0; p < P_; p++) {
            const float lx = cx + offp[(l * P_ + p) * 2 + 0] * hw;
            const float ly = cy + offp[(l * P_ + p) * 2 + 1] * hh;
            const float x = lx * (float)Wl - 0.5f;
            const float y = ly * (float)Hl - 0.5f;
            const float x0f = floorf(x), y0f = floorf(y);
            const int   x0 = (int)x0f,  y0 = (int)y0f;
            const float wx1 = x - x0f, wx0 = 1.f - wx1;
            const float wy1 = y - y0f, wy0 = 1.f - wy1;
            const float aw = w[l * P_ + p] * inv;

            const float fx0 = (x0 >= 0 && x0 < Wl)         ? 1.f : 0.f;
            const float fx1 = (x0 + 1 >= 0 && x0 + 1 < Wl) ? 1.f : 0.f;
            const float fy0 = (y0 >= 0 && y0 < Hl)         ? 1.f : 0.f;
            const float fy1 = (y0 + 1 >= 0 && y0 + 1 < Hl) ? 1.f : 0.f;

            const int xc0 = min(max(x0, 0), Wl - 1);
            const int xc1 = min(max(x0 + 1, 0), Wl - 1);
            const int yc0 = min(max(y0, 0), Hl - 1);
            const int yc1 = min(max(y0 + 1, 0), Hl - 1);

            const float cw00 = aw * wy0 * wx0 * fy0 * fx0;
            const float cw10 = aw * wy0 * wx1 * fy0 * fx1;
            const float cw01 = aw * wy1 * wx0 * fy1 * fx0;
            const float cw11 = aw * wy1 * wx1 * fy1 * fx1;
            wsum += cw00 + cw10 + cw01 + cw11;

            const size_t i00 = (size_t)(s0 + yc0 * Wl + xc0) * 32;  // uint4 units
            const size_t i10 = (size_t)(s0 + yc0 * Wl + xc1) * 32;
            const size_t i01 = (size_t)(s0 + yc1 * Wl + xc0) * 32;
            const size_t i11 = (size_t)(s0 + yc1 * Wl + xc1) * 32;

            uint4 r00 = vb[i00 + lane];
            uint4 r10 = vb[i10 + lane];
            uint4 r01 = vb[i01 + lane];
            uint4 r11 = vb[i11 + lane];

            const half2* h00 = (const half2*)&r00;
            const half2* h10 = (const half2*)&r10;
            const half2* h01 = (const half2*)&r01;
            const half2* h11 = (const half2*)&r11;
#pragma unroll
            for (int j = 0; j < 4; j++) {
                float2 f;
                f = __half22float2(h00[j]); acc[2*j] += cw00 * f.x; acc[2*j+1] += cw00 * f.y;
                f = __half22float2(h10[j]); acc[2*j] += cw10 * f.x; acc[2*j+1] += cw10 * f.y;
                f = __half22float2(h01[j]); acc[2*j] += cw01 * f.x; acc[2*j+1] += cw01 * f.y;
                f = __half22float2(h11[j]); acc[2*j] += cw11 * f.x; acc[2*j+1] += cw11 * f.y;
            }
        }
    }

    // stage raw sample to smem: lane owns channels [8*lane, 8*lane+8)
    ((float4*)sraw[warp])[2 * lane]     = make_float4(acc[0], acc[1], acc[2], acc[3]);
    ((float4*)sraw[warp])[2 * lane + 1] = make_float4(acc[4], acc[5], acc[6], acc[7]);

    __syncthreads();

    // projection: out[j] = sum_c raw[c] * Wv[c, h*32+j]
    float o = 0.f;
    const float* rw = sraw[warp];
#pragma unroll 16
    for (int c = 0; c < 256; c++)
        o += rw[c] * sWv[c][lane];

    o += wsum * bv[h * HD_ + lane];
    samp[(size_t)bq * D_ + h * HD_ + lane] = o;
}

// ---------------------------------------------------------------------------
// Launch
// ---------------------------------------------------------------------------
extern "C" void kernel_launch(void* const* d_in, const int* in_sizes, int n_in,
                              void* d_out, int out_size)
{
    const float* query = (const float*)d_in[0];
    const float* rp    = (const float*)d_in[1];
    const float* value = (const float*)d_in[2];
    const float* Wv    = (const float*)d_in[5];
    const float* bv    = (const float*)d_in[6];
    const float* Woff  = (const float*)d_in[7];
    const float* boff  = (const float*)d_in[8];
    const float* Wattn = (const float*)d_in[9];
    const float* battn = (const float*)d_in[10];
    const float* Wout  = (const float*)d_in[11];
    const float* bout  = (const float*)d_in[12];
    float* out = (float*)d_out;

    __half* vhalf;
    float *qfb, *samp, *Wqf, *bqf;
    cudaGetSymbolAddress((void**)&vhalf, g_vhalf);
    cudaGetSymbolAddress((void**)&qfb,   g_qf);
    cudaGetSymbolAddress((void**)&samp,  g_samp);
    cudaGetSymbolAddress((void**)&Wqf,   g_Wqf);
    cudaGetSymbolAddress((void**)&bqf,   g_bqf);

    const int Mq = B_ * LQ_;     // 9600

    // 0) value fp32 -> fp16
    {
        const int n8 = (B_ * LV_ * D_) / 8;   // 8,601,600
        f2h_kernel<<<(n8 + 255) / 256, 256>>>(value, vhalf, n8);
    }
    // 0b) fused query-side weights
    prep_weights_kernel<<<(256 * 288 + 255) / 256, 256>>>(Woff, boff, Wattn, battn, Wqf, bqf);

    // 1) fused offsets+attn: [Mq,256] @ [256,288] + bqf
    {
        const int N = 288;
        dim3 grid((N + BN - 1) / BN, (Mq + BM - 1) / BM);
        gemm_bias_kernel<<<grid, 256>>>(query, Wqf, bqf, qfb, Mq, N, D_);
    }
    // 2) fused softmax + fp16 bilinear sampling + per-head projection
    {
        dim3 grid(H_, Mq / QW);   // (8, 1200)
        sample_fused_kernel<<<grid, 256>>>(rp, qfb, vhalf, Wv, bv, samp);
    }
    // 3) output projection: [Mq,256] @ [256,256] + bout -> d_out
    {
        dim3 grid((D_ + BN - 1) / BN, (Mq + BM - 1) / BM);
        gemm_bias_kernel<<<grid, 256>>>(samp, Wout, bout, out, Mq, D_, D_);
    }
}

// round 4
// speedup vs baseline: 1.1379x; 1.1379x over previous
#include <cuda_runtime.h>
#include <cstdint>

// ---------------------------------------------------------------------------
// Problem constants
// ---------------------------------------------------------------------------
#define B_   32
#define LQ_  300
#define D_   256
#define H_   8
#define L_   3
#define P_   4
#define HD_  32
#define LV_  8400   // 80*80 + 40*40 + 20*20

// ---------------------------------------------------------------------------
// Scratch (device globals)
// ---------------------------------------------------------------------------
__device__ float g_qf  [(size_t)B_ * LQ_ * 288];          // fused off|attn [9600,288]
__device__ float g_raw [(size_t)B_ * LQ_ * H_ * D_];      // [9600, 8, 256] = 78.6 MB
__device__ float g_wsum[(size_t)B_ * LQ_ * H_];           // [9600, 8]
__device__ float g_samp[(size_t)B_ * LQ_ * D_];           // [9600, 256]
__device__ float g_Wqf [256 * 288];
__device__ float g_bqf [288];

// ---------------------------------------------------------------------------
// Build fused query-side weights: Wqf[256,288] = [Woff | Wattn]
// ---------------------------------------------------------------------------
__global__ __launch_bounds__(256)
void prep_weights_kernel(const float* __restrict__ Woff, const float* __restrict__ boff,
                         const float* __restrict__ Wattn, const float* __restrict__ battn,
                         float* __restrict__ Wqf, float* __restrict__ bqf)
{
    int i = blockIdx.x * blockDim.x + threadIdx.x;
    if (i < 256 * 288) {
        int k = i / 288, j = i % 288;
        Wqf[i] = (j < 192) ? Woff[k * 192 + j] : Wattn[k * 96 + (j - 192)];
    }
    if (i < 288)
        bqf[i] = (i < 192) ? boff[i] : battn[i - 192];
}

// ---------------------------------------------------------------------------
// Tiled GEMM:  C[M,N] = A[M,K] @ W[K,N] + bias[N]
// ---------------------------------------------------------------------------
#define BM 64
#define BN 64
#define BK 16

__global__ __launch_bounds__(256)
void gemm_bias_kernel(const float* __restrict__ A, const float* __restrict__ W,
                      const float* __restrict__ bias, float* __restrict__ C,
                      int M, int N, int K)
{
    __shared__ float As[BK][BM + 1];
    __shared__ float Bs[BK][BN];

    const int tid = threadIdx.x;
    const int m0  = blockIdx.y * BM;
    const int n0  = blockIdx.x * BN;
    const int ty  = tid >> 4;
    const int tx  = tid & 15;

    float acc[4][4];
#pragma unroll
    for (int i = 0; i < 4; i++)
#pragma unroll
        for (int j = 0; j < 4; j++) acc[i][j] = 0.f;

    for (int k0 = 0; k0 < K; k0 += BK) {
#pragma unroll
        for (int t = 0; t < 4; t++) {
            int idx = tid + t * 256;
            int m = idx >> 4;
            int k = idx & 15;
            int gm = m0 + m;
            As[k][m] = (gm < M) ? A[(size_t)gm * K + (k0 + k)] : 0.f;
        }
#pragma unroll
        for (int t = 0; t < 4; t++) {
            int idx = tid + t * 256;
            int k = idx >> 6;
            int n = idx & 63;
            int gn = n0 + n;
            Bs[k][n] = (gn < N) ? W[(size_t)(k0 + k) * N + gn] : 0.f;
        }
        __syncthreads();

#pragma unroll
        for (int k = 0; k < BK; k++) {
            float a[4], b[4];
#pragma unroll
            for (int i = 0; i < 4; i++) a[i] = As[k][ty + i * 16];
#pragma unroll
            for (int j = 0; j < 4; j++) b[j] = Bs[k][tx + j * 16];
#pragma unroll
            for (int i = 0; i < 4; i++)
#pragma unroll
                for (int j = 0; j < 4; j++)
                    acc[i][j] += a[i] * b[j];
        }
        __syncthreads();
    }

#pragma unroll
    for (int i = 0; i < 4; i++) {
        int gm = m0 + ty + i * 16;
        if (gm >= M) continue;
#pragma unroll
        for (int j = 0; j < 4; j++) {
            int gn = n0 + tx + j * 16;
            if (gn < N)
                C[(size_t)gm * N + gn] = acc[i][j] + bias[gn];
        }
    }
}

// ---------------------------------------------------------------------------
// Sampling kernel (gather only): warp <-> head, CTA <-> (b,q).
// Writes raw[bq, h, 256] = sum over 48 corners of cw * value[b, idx, :]
// and wsum[bq, h]. No projection here (that was the L1 bottleneck in R2).
// ---------------------------------------------------------------------------
__global__ __launch_bounds__(256)
void sample_raw_kernel(const float* __restrict__ rp,
                       const float* __restrict__ qf,     // [9600,288] off|attn
                       const float* __restrict__ value,  // [B, LV, 256] fp32
                       float* __restrict__ raw,          // [9600, 8, 256]
                       float* __restrict__ wsumb)        // [9600, 8]
{
    const int bq   = blockIdx.x;          // [0, 9600)
    const int h    = threadIdx.x >> 5;    // warp = head
    const int lane = threadIdx.x & 31;
    const int b    = bq / LQ_;

    // softmax over 12 logits (lane-redundant)
    const float* al = qf + (size_t)bq * 288 + 192 + h * (L_ * P_);
    float w[L_ * P_];
    float mx = -1e30f;
#pragma unroll
    for (int i = 0; i < L_ * P_; i++) { w[i] = al[i]; mx = fmaxf(mx, w[i]); }
    float ssum = 0.f;
#pragma unroll
    for (int i = 0; i < L_ * P_; i++) { w[i] = __expf(w[i] - mx); ssum += w[i]; }
    const float inv = 1.f / ssum;

    const float* offp = qf + (size_t)bq * 288 + h * (L_ * P_ * 2);
    const float* rpp  = rp + (size_t)bq * (L_ * 4);
    const float4* vb  = (const float4*)(value + (size_t)b * LV_ * D_);  // row = 64 float4

    float4 a0 = make_float4(0.f, 0.f, 0.f, 0.f);   // channels 4*lane..+3
    float4 a1 = make_float4(0.f, 0.f, 0.f, 0.f);   // channels 128+4*lane..+3
    float wsum = 0.f;

    const int HsA[3] = {80, 40, 20};
    const int stA[3] = {0, 6400, 8000};

#pragma unroll
    for (int l = 0; l < L_; l++) {
        const float cx = rpp[l * 4 + 0];
        const float cy = rpp[l * 4 + 1];
        const float hw = rpp[l * 4 + 2] * 0.5f;
        const float hh = rpp[l * 4 + 3] * 0.5f;
        const int Wl = HsA[l], Hl = HsA[l], s0 = stA[l];

#pragma unroll
        for (int p = 0; p < P_; p++) {
            const float lx = cx + offp[(l * P_ + p) * 2 + 0] * hw;
            const float ly = cy + offp[(l * P_ + p) * 2 + 1] * hh;
            const float x = lx * (float)Wl - 0.5f;
            const float y = ly * (float)Hl - 0.5f;
            const float x0f = floorf(x), y0f = floorf(y);
            const int   x0 = (int)x0f,  y0 = (int)y0f;
            const float wx1 = x - x0f, wx0 = 1.f - wx1;
            const float wy1 = y - y0f, wy0 = 1.f - wy1;
            const float aw = w[l * P_ + p] * inv;

            const float fx0 = (x0 >= 0 && x0 < Wl)         ? 1.f : 0.f;
            const float fx1 = (x0 + 1 >= 0 && x0 + 1 < Wl) ? 1.f : 0.f;
            const float fy0 = (y0 >= 0 && y0 < Hl)         ? 1.f : 0.f;
            const float fy1 = (y0 + 1 >= 0 && y0 + 1 < Hl) ? 1.f : 0.f;

            const int xc0 = min(max(x0, 0), Wl - 1);
            const int xc1 = min(max(x0 + 1, 0), Wl - 1);
            const int yc0 = min(max(y0, 0), Hl - 1);
            const int yc1 = min(max(y0 + 1, 0), Hl - 1);

            const float cw00 = aw * wy0 * wx0 * fy0 * fx0;
            const float cw10 = aw * wy0 * wx1 * fy0 * fx1;
            const float cw01 = aw * wy1 * wx0 * fy1 * fx0;
            const float cw11 = aw * wy1 * wx1 * fy1 * fx1;
            wsum += cw00 + cw10 + cw01 + cw11;

            const size_t i00 = (size_t)(s0 + yc0 * Wl + xc0) * 64;  // float4 units
            const size_t i10 = (size_t)(s0 + yc0 * Wl + xc1) * 64;
            const size_t i01 = (size_t)(s0 + yc1 * Wl + xc0) * 64;
            const size_t i11 = (size_t)(s0 + yc1 * Wl + xc1) * 64;

            // hoist all 8 loads (max MLP), then FMA
            float4 r00a = vb[i00 + lane], r00b = vb[i00 + lane + 32];
            float4 r10a = vb[i10 + lane], r10b = vb[i10 + lane + 32];
            float4 r01a = vb[i01 + lane], r01b = vb[i01 + lane + 32];
            float4 r11a = vb[i11 + lane], r11b = vb[i11 + lane + 32];

            a0.x += cw00 * r00a.x; a0.y += cw00 * r00a.y; a0.z += cw00 * r00a.z; a0.w += cw00 * r00a.w;
            a1.x += cw00 * r00b.x; a1.y += cw00 * r00b.y; a1.z += cw00 * r00b.z; a1.w += cw00 * r00b.w;
            a0.x += cw10 * r10a.x; a0.y += cw10 * r10a.y; a0.z += cw10 * r10a.z; a0.w += cw10 * r10a.w;
            a1.x += cw10 * r10b.x; a1.y += cw10 * r10b.y; a1.z += cw10 * r10b.z; a1.w += cw10 * r10b.w;
            a0.x += cw01 * r01a.x; a0.y += cw01 * r01a.y; a0.z += cw01 * r01a.z; a0.w += cw01 * r01a.w;
            a1.x += cw01 * r01b.x; a1.y += cw01 * r01b.y; a1.z += cw01 * r01b.z; a1.w += cw01 * r01b.w;
            a0.x += cw11 * r11a.x; a0.y += cw11 * r11a.y; a0.z += cw11 * r11a.z; a0.w += cw11 * r11a.w;
            a1.x += cw11 * r11b.x; a1.y += cw11 * r11b.y; a1.z += cw11 * r11b.z; a1.w += cw11 * r11b.w;
        }
    }

    // coalesced raw write: channels 4*lane and 128+4*lane
    float4* rr = (float4*)(raw + ((size_t)bq * H_ + h) * D_);
    rr[lane]      = a0;
    rr[lane + 32] = a1;
    if (lane == 0) wsumb[(size_t)bq * H_ + h] = wsum;
}

// ---------------------------------------------------------------------------
// Block-diagonal per-head projection:
//   samp[m, h*32+n] = sum_c raw[m, h, c] * Wv[c, h*32+n] + wsum[m,h]*bv[h*32+n]
// Grid: (m-tiles, heads). BM=64, N=32, BK=32, 256 threads, 4x2 micro-tile.
// ---------------------------------------------------------------------------
__global__ __launch_bounds__(256)
void proj_head_kernel(const float* __restrict__ raw,   // [9600, 8, 256]
                      const float* __restrict__ wsumb, // [9600, 8]
                      const float* __restrict__ Wv,    // [256, 256]
                      const float* __restrict__ bv,    // [256]
                      float* __restrict__ samp)        // [9600, 256]
{
    __shared__ float As[32][BM + 1];   // [k][m]
    __shared__ float Bs[32][32];       // [k][n]

    const int h   = blockIdx.y;
    const int m0  = blockIdx.x * BM;
    const int tid = threadIdx.x;
    const int ty  = tid >> 4;   // 0..15 -> rows
    const int tx  = tid & 15;   // 0..15 -> cols (2 each)

    float acc[4][2];
#pragma unroll
    for (int i = 0; i < 4; i++) { acc[i][0] = 0.f; acc[i][1] = 0.f; }

    const float* Ab = raw + ((size_t)m0 * H_ + h) * D_;  // row m: +m*2048
    const float* Bb = Wv + h * HD_;                      // Wv[c][h*32+n]

    for (int k0 = 0; k0 < D_; k0 += 32) {
        // A tile: 64 rows x 32 k  (2048 elems, 8/thread)
#pragma unroll
        for (int t = 0; t < 8; t++) {
            int idx = tid + t * 256;
            int m = idx >> 5, k = idx & 31;
            As[k][m] = Ab[(size_t)m * (H_ * D_) + k0 + k];
        }
        // B tile: 32 k x 32 n (1024 elems, 4/thread)
#pragma unroll
        for (int t = 0; t < 4; t++) {
            int idx = tid + t * 256;
            int k = idx >> 5, n = idx & 31;
            Bs[k][n] = Bb[(size_t)(k0 + k) * D_ + n];
        }
        __syncthreads();

#pragma unroll
        for (int k = 0; k < 32; k++) {
            float a[4], b0, b1;
#pragma unroll
            for (int i = 0; i < 4; i++) a[i] = As[k][ty + i * 16];
            b0 = Bs[k][tx];
            b1 = Bs[k][tx + 16];
#pragma unroll
            for (int i = 0; i < 4; i++) {
                acc[i][0] += a[i] * b0;
                acc[i][1] += a[i] * b1;
            }
        }
        __syncthreads();
    }

    const float bv0 = bv[h * HD_ + tx];
    const float bv1 = bv[h * HD_ + tx + 16];
#pragma unroll
    for (int i = 0; i < 4; i++) {
        int m = m0 + ty + i * 16;
        float ws = wsumb[(size_t)m * H_ + h];
        samp[(size_t)m * D_ + h * HD_ + tx]      = acc[i][0] + ws * bv0;
        samp[(size_t)m * D_ + h * HD_ + tx + 16] = acc[i][1] + ws * bv1;
    }
}

// ---------------------------------------------------------------------------
// Launch
// ---------------------------------------------------------------------------
extern "C" void kernel_launch(void* const* d_in, const int* in_sizes, int n_in,
                              void* d_out, int out_size)
{
    const float* query = (const float*)d_in[0];
    const float* rp    = (const float*)d_in[1];
    const float* value = (const float*)d_in[2];
    const float* Wv    = (const float*)d_in[5];
    const float* bv    = (const float*)d_in[6];
    const float* Woff  = (const float*)d_in[7];
    const float* boff  = (const float*)d_in[8];
    const float* Wattn = (const float*)d_in[9];
    const float* battn = (const float*)d_in[10];
    const float* Wout  = (const float*)d_in[11];
    const float* bout  = (const float*)d_in[12];
    float* out = (float*)d_out;

    float *qfb, *rawb, *wsumb, *samp, *Wqf, *bqf;
    cudaGetSymbolAddress((void**)&qfb,   g_qf);
    cudaGetSymbolAddress((void**)&rawb,  g_raw);
    cudaGetSymbolAddress((void**)&wsumb, g_wsum);
    cudaGetSymbolAddress((void**)&samp,  g_samp);
    cudaGetSymbolAddress((void**)&Wqf,   g_Wqf);
    cudaGetSymbolAddress((void**)&bqf,   g_bqf);

    const int Mq = B_ * LQ_;     // 9600

    // 0) fused query-side weights
    prep_weights_kernel<<<(256 * 288 + 255) / 256, 256>>>(Woff, boff, Wattn, battn, Wqf, bqf);

    // 1) fused offsets+attn: [Mq,256] @ [256,288]
    {
        const int N = 288;
        dim3 grid((N + BN - 1) / BN, (Mq + BM - 1) / BM);
        gemm_bias_kernel<<<grid, 256>>>(query, Wqf, bqf, qfb, Mq, N, D_);
    }
    // 2) gather-only sampler -> raw [9600,8,256], wsum [9600,8]
    sample_raw_kernel<<<Mq, 256>>>(rp, qfb, value, rawb, wsumb);

    // 3) per-head projection -> samp [9600,256]
    {
        dim3 grid(Mq / BM, H_);   // (150, 8)
        proj_head_kernel<<<grid, 256>>>(rawb, wsumb, Wv, bv, samp);
    }
    // 4) output projection -> d_out
    {
        dim3 grid((D_ + BN - 1) / BN, (Mq + BM - 1) / BM);
        gemm_bias_kernel<<<grid, 256>>>(samp, Wout, bout, out, Mq, D_, D_);
    }
}

// round 5
// speedup vs baseline: 1.3808x; 1.2134x over previous
#include <cuda_runtime.h>
#include <cstdint>

// ---------------------------------------------------------------------------
// Problem constants
// ---------------------------------------------------------------------------
#define B_   32
#define LQ_  300
#define D_   256
#define H_   8
#define L_   3
#define P_   4
#define HD_  32
#define LV_  8400   // 80*80 + 40*40 + 20*20
#define NQF  320    // padded fused off|attn width (192 off + 96 attn + 32 pad)

// ---------------------------------------------------------------------------
// Scratch (device globals)
// ---------------------------------------------------------------------------
__device__ float g_qf  [(size_t)B_ * LQ_ * NQF];          // [9600,320]
__device__ float g_raw [(size_t)B_ * LQ_ * H_ * D_];      // [9600, 8, 256]
__device__ float g_wsum[(size_t)B_ * LQ_ * H_];           // [9600, 8]
__device__ float g_samp[(size_t)B_ * LQ_ * D_];           // [9600, 256]
__device__ float g_Wqf [256 * NQF];
__device__ float g_bqf [NQF];

// ---------------------------------------------------------------------------
// Build fused (padded) query-side weights: Wqf[256,320] = [Woff | Wattn | 0]
// ---------------------------------------------------------------------------
__global__ __launch_bounds__(256)
void prep_weights_kernel(const float* __restrict__ Woff, const float* __restrict__ boff,
                         const float* __restrict__ Wattn, const float* __restrict__ battn,
                         float* __restrict__ Wqf, float* __restrict__ bqf)
{
    int i = blockIdx.x * blockDim.x + threadIdx.x;
    if (i < 256 * NQF) {
        int k = i / NQF, j = i % NQF;
        float v = 0.f;
        if (j < 192)      v = Woff[k * 192 + j];
        else if (j < 288) v = Wattn[k * 96 + (j - 192)];
        Wqf[i] = v;
    }
    if (i < NQF) {
        float v = 0.f;
        if (i < 192)      v = boff[i];
        else if (i < 288) v = battn[i - 192];
        bqf[i] = v;
    }
}

// ---------------------------------------------------------------------------
// Tiled GEMM, no guards:  C[M,N] = A[M,K] @ W[K,N] + bias[N]
// Requires M%128==0, N%64==0, K%32==0.
// BM=128, BN=64, BK=32; 256 threads; 8x4 micro-tile on consecutive rows/cols
// -> inner loop = 3x LDS.128 + 32 FMA per k.
// ---------------------------------------------------------------------------
__global__ __launch_bounds__(256)
void gemm_bias128(const float* __restrict__ A, const float* __restrict__ W,
                  const float* __restrict__ bias, float* __restrict__ C,
                  int N, int K)
{
    __shared__ __align__(16) float As[32][132];   // [k][m], 528B row (16B mult)
    __shared__ __align__(16) float Bs[32][64];

    const int tid = threadIdx.x;
    const int m0  = blockIdx.y * 128;
    const int n0  = blockIdx.x * 64;
    const int ty  = tid >> 4;    // 0..15 : rows ty*8 .. ty*8+7
    const int tx  = tid & 15;    // 0..15 : cols tx*4 .. tx*4+3

    const int am  = tid >> 3;    // A-load row base (+t*32)
    const int akq = tid & 7;     // A-load float4 index in row
    const int bk  = tid >> 4;    // B-load k base (+t*16)
    const int bnq = tid & 15;    // B-load float4 col index

    float acc[8][4];
#pragma unroll
    for (int i = 0; i < 8; i++)
#pragma unroll
        for (int j = 0; j < 4; j++) acc[i][j] = 0.f;

    for (int k0 = 0; k0 < K; k0 += 32) {
        // A tile: 128 rows x 32 k = 1024 float4, 4 per thread (full 128B rows)
#pragma unroll
        for (int t = 0; t < 4; t++) {
            int m = am + t * 32;
            float4 v = *(const float4*)(A + (size_t)(m0 + m) * K + k0 + akq * 4);
            As[akq * 4 + 0][m] = v.x;
            As[akq * 4 + 1][m] = v.y;
            As[akq * 4 + 2][m] = v.z;
            As[akq * 4 + 3][m] = v.w;
        }
        // B tile: 32 k x 64 n = 512 float4, 2 per thread
#pragma unroll
        for (int t = 0; t < 2; t++) {
            int k = bk + t * 16;
            *(float4*)&Bs[k][bnq * 4] =
                *(const float4*)(W + (size_t)(k0 + k) * N + n0 + bnq * 4);
        }
        __syncthreads();

#pragma unroll
        for (int k = 0; k < 32; k++) {
            float4 a0 = *(const float4*)&As[k][ty * 8];
            float4 a1 = *(const float4*)&As[k][ty * 8 + 4];
            float4 b  = *(const float4*)&Bs[k][tx * 4];
            float av[8] = {a0.x, a0.y, a0.z, a0.w, a1.x, a1.y, a1.z, a1.w};
#pragma unroll
            for (int i = 0; i < 8; i++) {
                acc[i][0] += av[i] * b.x;
                acc[i][1] += av[i] * b.y;
                acc[i][2] += av[i] * b.z;
                acc[i][3] += av[i] * b.w;
            }
        }
        __syncthreads();
    }

    float4 bb = *(const float4*)(bias + n0 + tx * 4);
#pragma unroll
    for (int i = 0; i < 8; i++) {
        int m = m0 + ty * 8 + i;
        float4 o = make_float4(acc[i][0] + bb.x, acc[i][1] + bb.y,
                               acc[i][2] + bb.z, acc[i][3] + bb.w);
        *(float4*)(C + (size_t)m * N + n0 + tx * 4) = o;
    }
}

// ---------------------------------------------------------------------------
// Sampling kernel (gather only): warp <-> head, CTA <-> (b,q).
// ---------------------------------------------------------------------------
__global__ __launch_bounds__(256)
void sample_raw_kernel(const float* __restrict__ rp,
                       const float* __restrict__ qf,     // [9600,320] off|attn
                       const float* __restrict__ value,  // [B, LV, 256] fp32
                       float* __restrict__ raw,          // [9600, 8, 256]
                       float* __restrict__ wsumb)        // [9600, 8]
{
    const int bq   = blockIdx.x;
    const int h    = threadIdx.x >> 5;
    const int lane = threadIdx.x & 31;
    const int b    = bq / LQ_;

    const float* al = qf + (size_t)bq * NQF + 192 + h * (L_ * P_);
    float w[L_ * P_];
    float mx = -1e30f;
#pragma unroll
    for (int i = 0; i < L_ * P_; i++) { w[i] = al[i]; mx = fmaxf(mx, w[i]); }
    float ssum = 0.f;
#pragma unroll
    for (int i = 0; i < L_ * P_; i++) { w[i] = __expf(w[i] - mx); ssum += w[i]; }
    const float inv = 1.f / ssum;

    const float* offp = qf + (size_t)bq * NQF + h * (L_ * P_ * 2);
    const float* rpp  = rp + (size_t)bq * (L_ * 4);
    const float4* vb  = (const float4*)(value + (size_t)b * LV_ * D_);

    float4 a0 = make_float4(0.f, 0.f, 0.f, 0.f);
    float4 a1 = make_float4(0.f, 0.f, 0.f, 0.f);
    float wsum = 0.f;

    const int HsA[3] = {80, 40, 20};
    const int stA[3] = {0, 6400, 8000};

#pragma unroll
    for (int l = 0; l < L_; l++) {
        const float cx = rpp[l * 4 + 0];
        const float cy = rpp[l * 4 + 1];
        const float hw = rpp[l * 4 + 2] * 0.5f;
        const float hh = rpp[l * 4 + 3] * 0.5f;
        const int Wl = HsA[l], Hl = HsA[l], s0 = stA[l];

#pragma unroll
        for (int p = 0; p < P_; p++) {
            const float lx = cx + offp[(l * P_ + p) * 2 + 0] * hw;
            const float ly = cy + offp[(l * P_ + p) * 2 + 1] * hh;
            const float x = lx * (float)Wl - 0.5f;
            const float y = ly * (float)Hl - 0.5f;
            const float x0f = floorf(x), y0f = floorf(y);
            const int   x0 = (int)x0f,  y0 = (int)y0f;
            const float wx1 = x - x0f, wx0 = 1.f - wx1;
            const float wy1 = y - y0f, wy0 = 1.f - wy1;
            const float aw = w[l * P_ + p] * inv;

            const float fx0 = (x0 >= 0 && x0 < Wl)         ? 1.f : 0.f;
            const float fx1 = (x0 + 1 >= 0 && x0 + 1 < Wl) ? 1.f : 0.f;
            const float fy0 = (y0 >= 0 && y0 < Hl)         ? 1.f : 0.f;
            const float fy1 = (y0 + 1 >= 0 && y0 + 1 < Hl) ? 1.f : 0.f;

            const int xc0 = min(max(x0, 0), Wl - 1);
            const int xc1 = min(max(x0 + 1, 0), Wl - 1);
            const int yc0 = min(max(y0, 0), Hl - 1);
            const int yc1 = min(max(y0 + 1, 0), Hl - 1);

            const float cw00 = aw * wy0 * wx0 * fy0 * fx0;
            const float cw10 = aw * wy0 * wx1 * fy0 * fx1;
            const float cw01 = aw * wy1 * wx0 * fy1 * fx0;
            const float cw11 = aw * wy1 * wx1 * fy1 * fx1;
            wsum += cw00 + cw10 + cw01 + cw11;

            const size_t i00 = (size_t)(s0 + yc0 * Wl + xc0) * 64;
            const size_t i10 = (size_t)(s0 + yc0 * Wl + xc1) * 64;
            const size_t i01 = (size_t)(s0 + yc1 * Wl + xc0) * 64;
            const size_t i11 = (size_t)(s0 + yc1 * Wl + xc1) * 64;

            float4 r00a = vb[i00 + lane], r00b = vb[i00 + lane + 32];
            float4 r10a = vb[i10 + lane], r10b = vb[i10 + lane + 32];
            float4 r01a = vb[i01 + lane], r01b = vb[i01 + lane + 32];
            float4 r11a = vb[i11 + lane], r11b = vb[i11 + lane + 32];

            a0.x += cw00 * r00a.x; a0.y += cw00 * r00a.y; a0.z += cw00 * r00a.z; a0.w += cw00 * r00a.w;
            a1.x += cw00 * r00b.x; a1.y += cw00 * r00b.y; a1.z += cw00 * r00b.z; a1.w += cw00 * r00b.w;
            a0.x += cw10 * r10a.x; a0.y += cw10 * r10a.y; a0.z += cw10 * r10a.z; a0.w += cw10 * r10a.w;
            a1.x += cw10 * r10b.x; a1.y += cw10 * r10b.y; a1.z += cw10 * r10b.z; a1.w += cw10 * r10b.w;
            a0.x += cw01 * r01a.x; a0.y += cw01 * r01a.y; a0.z += cw01 * r01a.z; a0.w += cw01 * r01a.w;
            a1.x += cw01 * r01b.x; a1.y += cw01 * r01b.y; a1.z += cw01 * r01b.z; a1.w += cw01 * r01b.w;
            a0.x += cw11 * r11a.x; a0.y += cw11 * r11a.y; a0.z += cw11 * r11a.z; a0.w += cw11 * r11a.w;
            a1.x += cw11 * r11b.x; a1.y += cw11 * r11b.y; a1.z += cw11 * r11b.z; a1.w += cw11 * r11b.w;
        }
    }

    float4* rr = (float4*)(raw + ((size_t)bq * H_ + h) * D_);
    rr[lane]      = a0;
    rr[lane + 32] = a1;
    if (lane == 0) wsumb[(size_t)bq * H_ + h] = wsum;
}

// ---------------------------------------------------------------------------
// Block-diagonal per-head projection:
//   samp[m, h*32+n] = sum_c raw[m, h, c] * Wv[c, h*32+n] + wsum[m,h]*bv[h*32+n]
// BM=128, N=32, BK=32; 256 threads; 4x4 micro on consecutive rows/cols
// -> inner loop = 2x LDS.128 + 16 FMA per k.
// ---------------------------------------------------------------------------
__global__ __launch_bounds__(256)
void proj_head_kernel(const float* __restrict__ raw,   // [9600, 8, 256]
                      const float* __restrict__ wsumb, // [9600, 8]
                      const float* __restrict__ Wv,    // [256, 256]
                      const float* __restrict__ bv,    // [256]
                      float* __restrict__ samp)        // [9600, 256]
{
    __shared__ __align__(16) float As[32][132];   // [k][m]
    __shared__ __align__(16) float Bs[32][32];    // [k][n]

    const int h   = blockIdx.y;
    const int m0  = blockIdx.x * 128;
    const int tid = threadIdx.x;
    const int ty  = tid >> 3;   // 0..31 : rows ty*4..+3
    const int tx  = tid & 7;    // 0..7  : cols tx*4..+3

    const int am  = tid >> 3;   // A-load row base (+t*32)
    const int akq = tid & 7;    // A-load float4 idx (full 128B rows)
    const int blk = tid >> 3;   // B-load k
    const int bnq = tid & 7;    // B-load float4 col

    float acc[4][4];
#pragma unroll
    for (int i = 0; i < 4; i++)
#pragma unroll
        for (int j = 0; j < 4; j++) acc[i][j] = 0.f;

    const float* Ab = raw + ((size_t)m0 * H_ + h) * D_;   // row stride 2048
    const float* Bb = Wv + h * HD_;

    for (int k0 = 0; k0 < D_; k0 += 32) {
#pragma unroll
        for (int t = 0; t < 4; t++) {
            int m = am + t * 32;
            float4 v = *(const float4*)(Ab + (size_t)m * (H_ * D_) + k0 + akq * 4);
            As[akq * 4 + 0][m] = v.x;
            As[akq * 4 + 1][m] = v.y;
            As[akq * 4 + 2][m] = v.z;
            As[akq * 4 + 3][m] = v.w;
        }
        *(float4*)&Bs[blk][bnq * 4] =
            *(const float4*)(Bb + (size_t)(k0 + blk) * D_ + bnq * 4);
        __syncthreads();

#pragma unroll
        for (int k = 0; k < 32; k++) {
            float4 a = *(const float4*)&As[k][ty * 4];
            float4 b = *(const float4*)&Bs[k][tx * 4];
            acc[0][0] += a.x * b.x; acc[0][1] += a.x * b.y; acc[0][2] += a.x * b.z; acc[0][3] += a.x * b.w;
            acc[1][0] += a.y * b.x; acc[1][1] += a.y * b.y; acc[1][2] += a.y * b.z; acc[1][3] += a.y * b.w;
            acc[2][0] += a.z * b.x; acc[2][1] += a.z * b.y; acc[2][2] += a.z * b.z; acc[2][3] += a.z * b.w;
            acc[3][0] += a.w * b.x; acc[3][1] += a.w * b.y; acc[3][2] += a.w * b.z; acc[3][3] += a.w * b.w;
        }
        __syncthreads();
    }

    float4 bvv = *(const float4*)(bv + h * HD_ + tx * 4);
#pragma unroll
    for (int i = 0; i < 4; i++) {
        int m = m0 + ty * 4 + i;
        float ws = wsumb[(size_t)m * H_ + h];
        float4 o = make_float4(acc[i][0] + ws * bvv.x, acc[i][1] + ws * bvv.y,
                               acc[i][2] + ws * bvv.z, acc[i][3] + ws * bvv.w);
        *(float4*)(samp + (size_t)m * D_ + h * HD_ + tx * 4) = o;
    }
}

// ---------------------------------------------------------------------------
// Launch
// ---------------------------------------------------------------------------
extern "C" void kernel_launch(void* const* d_in, const int* in_sizes, int n_in,
                              void* d_out, int out_size)
{
    const float* query = (const float*)d_in[0];
    const float* rp    = (const float*)d_in[1];
    const float* value = (const float*)d_in[2];
    const float* Wv    = (const float*)d_in[5];
    const float* bv    = (const float*)d_in[6];
    const float* Woff  = (const float*)d_in[7];
    const float* boff  = (const float*)d_in[8];
    const float* Wattn = (const float*)d_in[9];
    const float* battn = (const float*)d_in[10];
    const float* Wout  = (const float*)d_in[11];
    const float* bout  = (const float*)d_in[12];
    float* out = (float*)d_out;

    float *qfb, *rawb, *wsumb, *samp, *Wqf, *bqf;
    cudaGetSymbolAddress((void**)&qfb,   g_qf);
    cudaGetSymbolAddress((void**)&rawb,  g_raw);
    cudaGetSymbolAddress((void**)&wsumb, g_wsum);
    cudaGetSymbolAddress((void**)&samp,  g_samp);
    cudaGetSymbolAddress((void**)&Wqf,   g_Wqf);
    cudaGetSymbolAddress((void**)&bqf,   g_bqf);

    const int Mq = B_ * LQ_;     // 9600 (75 * 128)

    // 0) fused padded query-side weights
    prep_weights_kernel<<<(256 * NQF + 255) / 256, 256>>>(Woff, boff, Wattn, battn, Wqf, bqf);

    // 1) fused offsets+attn: [9600,256] @ [256,320]
    {
        dim3 grid(NQF / 64, Mq / 128);   // (5, 75)
        gemm_bias128<<<grid, 256>>>(query, Wqf, bqf, qfb, NQF, D_);
    }
    // 2) gather-only sampler -> raw [9600,8,256], wsum [9600,8]
    sample_raw_kernel<<<Mq, 256>>>(rp, qfb, value, rawb, wsumb);

    // 3) per-head projection -> samp [9600,256]
    {
        dim3 grid(Mq / 128, H_);   // (75, 8)
        proj_head_kernel<<<grid, 256>>>(rawb, wsumb, Wv, bv, samp);
    }
    // 4) output projection -> d_out
    {
        dim3 grid(D_ / 64, Mq / 128);   // (4, 75)
        gemm_bias128<<<grid, 256>>>(samp, Wout, bout, out, D_, D_);
    }
}